// round 1
// baseline (speedup 1.0000x reference)
#include <cuda_runtime.h>
#include <math_constants.h>
#include <cstdint>

// Problem constants (fixed by the dataset)
#define BB 4
#define MM 1024
#define NN 32768

// Tiling
#define NC      1024              // pc points per chunk (smem tile)
#define NCHUNK  (NN / NC)         // 32
#define MT      512               // keypoints per block
#define THREADS 128
#define KPT     (MT / THREADS)    // 4 keypoints per thread

// Scratch: per-keypoint running min of squared distance, as uint bits.
// d2 >= 0 always, so IEEE float ordering == uint ordering.
__device__ unsigned int g_min_d2[BB * MM];

__global__ void p2p_init_kernel() {
    int i = blockIdx.x * blockDim.x + threadIdx.x;
    if (i < BB * MM) g_min_d2[i] = 0x7f7fffffu;  // FLT_MAX bits
}

__global__ __launch_bounds__(THREADS)
void p2p_dist_kernel(const float* __restrict__ kp, const float* __restrict__ pc) {
    __shared__ float sx[NC];
    __shared__ float sy[NC];
    __shared__ float sz[NC];

    const int b     = blockIdx.z;
    const int mbase = blockIdx.y * MT;
    const int nbase = blockIdx.x * NC;

    // Load this block's pc chunk into shared memory (SoA)
    const float* pcb = pc + (size_t)b * 3 * NN + nbase;
    for (int i = threadIdx.x; i < NC; i += THREADS) {
        sx[i] = pcb[0 * NN + i];
        sy[i] = pcb[1 * NN + i];
        sz[i] = pcb[2 * NN + i];
    }
    __syncthreads();

    // Each thread owns KPT keypoints (strided by THREADS within the tile)
    const float* kb = kp + (size_t)b * 3 * MM;
    float kx[KPT], ky[KPT], kz[KPT], mn[KPT];
#pragma unroll
    for (int r = 0; r < KPT; r++) {
        int m = mbase + r * THREADS + threadIdx.x;
        kx[r] = kb[0 * MM + m];
        ky[r] = kb[1 * MM + m];
        kz[r] = kb[2 * MM + m];
        mn[r] = CUDART_INF_F;
    }

    // Inner loop: one broadcast LDS triple feeds KPT keypoint updates.
#pragma unroll 4
    for (int j = 0; j < NC; j++) {
        const float px = sx[j];
        const float py = sy[j];
        const float pz = sz[j];
#pragma unroll
        for (int r = 0; r < KPT; r++) {
            const float dx = kx[r] - px;
            const float dy = ky[r] - py;
            const float dz = kz[r] - pz;
            const float d2 = fmaf(dx, dx, fmaf(dy, dy, dz * dz));
            mn[r] = fminf(mn[r], d2);
        }
    }

    // Combine across N-chunks: atomicMin on the float bit pattern.
#pragma unroll
    for (int r = 0; r < KPT; r++) {
        int m = mbase + r * THREADS + threadIdx.x;
        atomicMin(&g_min_d2[b * MM + m], __float_as_uint(mn[r]));
    }
}

__global__ void p2p_reduce_kernel(float* __restrict__ out) {
    __shared__ float ssum[256];
    float s = 0.0f;
    for (int i = threadIdx.x; i < BB * MM; i += 256)
        s += sqrtf(__uint_as_float(g_min_d2[i]));
    ssum[threadIdx.x] = s;
    __syncthreads();
    for (int off = 128; off > 0; off >>= 1) {
        if (threadIdx.x < off) ssum[threadIdx.x] += ssum[threadIdx.x + off];
        __syncthreads();
    }
    if (threadIdx.x == 0) out[0] = ssum[0] * (1.0f / (float)(BB * MM));
}

extern "C" void kernel_launch(void* const* d_in, const int* in_sizes, int n_in,
                              void* d_out, int out_size) {
    const float* keypoints = (const float*)d_in[0];  // [B,3,M]
    const float* pc        = (const float*)d_in[1];  // [B,3,N]
    float* out             = (float*)d_out;          // scalar

    p2p_init_kernel<<<(BB * MM + 255) / 256, 256>>>();

    dim3 grid(NCHUNK, MM / MT, BB);   // 32 x 2 x 4 = 256 blocks
    p2p_dist_kernel<<<grid, THREADS>>>(keypoints, pc);

    p2p_reduce_kernel<<<1, 256>>>(out);
}

// round 2
// speedup vs baseline: 1.5092x; 1.5092x over previous
#include <cuda_runtime.h>
#include <math_constants.h>
#include <cstdint>

// Problem constants (fixed by the dataset)
#define BB 4
#define MM 1024
#define NN 32768

// Tiling
#define NC      256               // pc points per chunk (smem tile)
#define NCHUNK  (NN / NC)         // 128
#define MT      512               // keypoints per block
#define THREADS 128
#define KPT     (MT / THREADS)    // 4 keypoints per thread
#define NKEY    (BB * MM)         // 4096

// Per-chunk partial minima of d2 (already includes +k^2). No atomics, no init.
__device__ float g_partial[NCHUNK * NKEY];

// Reduce-stage scratch
#define RBLOCKS (NKEY / 256)      // 16
__device__ float        g_bsum[RBLOCKS];
__device__ unsigned int g_count;  // zero-init; reset by last block each call

__global__ __launch_bounds__(THREADS)
void p2p_dist_kernel(const float* __restrict__ kp, const float* __restrict__ pc) {
    __shared__ float4 sp[NC];     // (px, py, pz, p2)

    const int chunk = blockIdx.x;
    const int mbase = blockIdx.y * MT;
    const int b     = blockIdx.z;
    const int nbase = chunk * NC;

    // Fill smem tile: point coords + precomputed |p|^2
    const float* pcb = pc + (size_t)b * 3 * NN + nbase;
#pragma unroll
    for (int i = threadIdx.x; i < NC; i += THREADS) {
        float px = pcb[0 * NN + i];
        float py = pcb[1 * NN + i];
        float pz = pcb[2 * NN + i];
        float p2 = fmaf(px, px, fmaf(py, py, pz * pz));
        sp[i] = make_float4(px, py, pz, p2);
    }
    __syncthreads();

    // Keypoints: pre-scale by -2, keep |k|^2 to fold back after the min.
    const float* kb = kp + (size_t)b * 3 * MM;
    float ax[KPT], ay[KPT], az[KPT], c[KPT], mn[KPT];
#pragma unroll
    for (int r = 0; r < KPT; r++) {
        int m = mbase + r * THREADS + threadIdx.x;
        float kx = kb[0 * MM + m];
        float ky = kb[1 * MM + m];
        float kz = kb[2 * MM + m];
        c[r]  = fmaf(kx, kx, fmaf(ky, ky, kz * kz));
        ax[r] = -2.0f * kx;
        ay[r] = -2.0f * ky;
        az[r] = -2.0f * kz;
        mn[r] = CUDART_INF_F;
    }

    // Inner loop: 1 broadcast LDS.128 -> KPT x (3 FFMA + 1 FMNMX)
#pragma unroll 4
    for (int j = 0; j < NC; j++) {
        const float4 p = sp[j];
#pragma unroll
        for (int r = 0; r < KPT; r++) {
            float d2 = fmaf(ax[r], p.x, fmaf(ay[r], p.y, fmaf(az[r], p.z, p.w)));
            mn[r] = fminf(mn[r], d2);
        }
    }

    // Write per-chunk partial (includes +k^2), coalesced, no atomics.
    float* part = g_partial + (size_t)chunk * NKEY + b * MM;
#pragma unroll
    for (int r = 0; r < KPT; r++) {
        int m = mbase + r * THREADS + threadIdx.x;
        part[m] = mn[r] + c[r];
    }
}

__global__ __launch_bounds__(256)
void p2p_reduce_kernel(float* __restrict__ out) {
    __shared__ float ssum[256];
    __shared__ bool  amLast;

    const int i = blockIdx.x * 256 + threadIdx.x;   // keypoint index

    // Min across chunks (coalesced: stride NKEY between chunks)
    float mn = CUDART_INF_F;
#pragma unroll 8
    for (int cidx = 0; cidx < NCHUNK; cidx++)
        mn = fminf(mn, g_partial[(size_t)cidx * NKEY + i]);

    ssum[threadIdx.x] = sqrtf(fmaxf(mn, 0.0f));
    __syncthreads();
    for (int off = 128; off > 0; off >>= 1) {
        if (threadIdx.x < off) ssum[threadIdx.x] += ssum[threadIdx.x + off];
        __syncthreads();
    }
    if (threadIdx.x == 0) {
        g_bsum[blockIdx.x] = ssum[0];
        __threadfence();
        unsigned int prev = atomicAdd(&g_count, 1u);
        amLast = (prev == RBLOCKS - 1);
    }
    __syncthreads();

    if (amLast && threadIdx.x == 0) {
        float s = 0.0f;
#pragma unroll
        for (int k = 0; k < RBLOCKS; k++) s += g_bsum[k];
        out[0] = s * (1.0f / (float)NKEY);
        g_count = 0;   // reset for next graph replay (deterministic)
    }
}

extern "C" void kernel_launch(void* const* d_in, const int* in_sizes, int n_in,
                              void* d_out, int out_size) {
    const float* keypoints = (const float*)d_in[0];  // [B,3,M]
    const float* pc        = (const float*)d_in[1];  // [B,3,N]
    float* out             = (float*)d_out;          // scalar

    dim3 grid(NCHUNK, MM / MT, BB);   // 128 x 2 x 4 = 1024 blocks
    p2p_dist_kernel<<<grid, THREADS>>>(keypoints, pc);

    p2p_reduce_kernel<<<RBLOCKS, 256>>>(out);
}